// round 11
// baseline (speedup 1.0000x reference)
#include <cuda_runtime.h>
#include <cuda_fp16.h>
#include <stdint.h>

#define NTOK   262144
#define NSLOT  524288
#define DIN    128
#define DOUT   128
#define NEXP   8
#define TM     128            // slot rows per tile
#define NT     (NSLOT / TM)   // 4096 tiles
#define GRID   148
#define NTHR   512
#define SAR    132            // Araw padded stride (floats)

typedef unsigned long long ull;

__device__ __half g_ybuf[(size_t)NSLOT * DOUT];   // gate-scaled per-slot outputs (fp16)
__device__ unsigned g_bar = 0;                    // grid-barrier arrival counter
__device__ volatile unsigned g_gen = 0;           // grid-barrier generation (monotonic)

// ---------------------------------------------------------------------------
// helpers
// ---------------------------------------------------------------------------
__device__ __forceinline__ uint32_t smem_u32(const void* p) {
    uint32_t a;
    asm("{ .reg .u64 t; cvta.to.shared.u64 t, %1; cvt.u32.u64 %0, t; }" : "=r"(a) : "l"(p));
    return a;
}
// pack two fp32 -> fp16x2 (lo = x, hi = y)
__device__ __forceinline__ uint32_t pack_h2(float x, float y) {
    uint32_t u;
    asm("cvt.rn.f16x2.f32 %0, %1, %2;" : "=r"(u) : "f"(y), "f"(x));
    return u;
}
__device__ __forceinline__ void cp16(uint32_t dst, const void* src) {
    asm volatile("cp.async.ca.shared.global [%0], [%1], 16;" :: "r"(dst), "l"(src) : "memory");
}
#define CP_COMMIT() asm volatile("cp.async.commit_group;" ::: "memory")
#define CP_WAIT0()  asm volatile("cp.async.wait_group 0;" ::: "memory")

// m16n8k16 fp16 -> fp32 acc
__device__ __forceinline__ void mma_f16(float* d, const uint32_t* a, uint32_t b0, uint32_t b1) {
    asm volatile("mma.sync.aligned.m16n8k16.row.col.f32.f16.f16.f32 "
                 "{%0,%1,%2,%3}, {%4,%5,%6,%7}, {%8,%9}, {%0,%1,%2,%3};"
                 : "+f"(d[0]), "+f"(d[1]), "+f"(d[2]), "+f"(d[3])
                 : "r"(a[0]), "r"(a[1]), "r"(a[2]), "r"(a[3]), "r"(b0), "r"(b1));
}

// ---------------------------------------------------------------------------
// Persistent fused kernel: grouped GEMM (fp16 mma.sync) -> grid barrier ->
// gated combine. 512 threads, grid = 148 = #SMs (all CTAs co-resident, so the
// software grid barrier cannot deadlock).
// ---------------------------------------------------------------------------
__global__ void __launch_bounds__(NTHR, 1)
k_moe(const float* __restrict__ inputs,
      const float* __restrict__ weight,   // [E][DOUT][DIN] == W[n][k] row-major
      const float* __restrict__ gates,    // flat [NSLOT]
      const int*   __restrict__ sei,
      const int*   __restrict__ ssi,
      float* __restrict__ out)
{
    extern __shared__ float smraw[];
    float* Araw   = smraw;                                   // 128*SAR f32
    uint4* As_frag = (uint4*)(smraw + 128 * SAR);            // 2048 uint4
    uint4* B_frag  = As_frag + 8 * 8 * 32;                   // 2048 uint4

    __shared__ int   ss2[2][TM];
    __shared__ float gt2[2][TM];
    __shared__ int   ex2[2][TM];
    __shared__ int   seg_e[NEXP + 1];
    __shared__ int   seg_n;

    const int tid  = threadIdx.x;
    const int lane = tid & 31;
    const int wid  = tid >> 5;        // 0..15
    const int wm   = wid >> 2;        // 0..3  -> rows wm*32
    const int wn   = wid & 3;         // 0..3  -> cols wn*32
    const int gr   = lane >> 2;       // 0..7
    const int tc   = lane & 3;        // 0..3

    // ---- prologue: metadata + first A prefetch ----
    const int t0 = blockIdx.x;
    if (tid < TM) {
        const int ss = ssi[t0 * TM + tid];
        ss2[0][tid] = ss;
        gt2[0][tid] = gates[ss];
        ex2[0][tid] = sei[t0 * TM + tid];
    }
    __syncthreads();
    {
        const uint32_t abase = smem_u32(Araw);
        #pragma unroll
        for (int it = 0; it < 8; ++it) {
            const int idx = tid + NTHR * it;          // 4096 float4 units
            const int m = idx >> 5, q = (idx & 31) * 4;
            cp16(abase + (uint32_t)(m * SAR + q) * 4,
                 inputs + (size_t)(ss2[0][m] >> 1) * DIN + q);
        }
    }
    CP_COMMIT();

    int par = 0;
    int B_cur = -1;

    for (int t = t0; t < NT; t += GRID) {
        CP_WAIT0();
        __syncthreads();   // Araw ready; prior-tile MMA done with As_frag

        // ---- cvt Araw(fp32) -> As_frag(fp16 fragments) ----
        {
            const int R = wid >> 1;
            const int ks0 = (wid & 1) * 4;
            const int row = R * 16 + gr;
            #pragma unroll
            for (int i = 0; i < 4; ++i) {
                const int ks = ks0 + i;
                const int c0 = ks * 16 + tc * 2;
                const float2 v00 = *(const float2*)(Araw + row * SAR + c0);
                const float2 v10 = *(const float2*)(Araw + (row + 8) * SAR + c0);
                const float2 v01 = *(const float2*)(Araw + row * SAR + c0 + 8);
                const float2 v11 = *(const float2*)(Araw + (row + 8) * SAR + c0 + 8);
                uint4 f;
                f.x = pack_h2(v00.x, v00.y);
                f.y = pack_h2(v10.x, v10.y);
                f.z = pack_h2(v01.x, v01.y);
                f.w = pack_h2(v11.x, v11.y);
                As_frag[(R * 8 + ks) * 32 + lane] = f;
            }
        }
        __syncthreads();   // Araw free, As_frag ready

        // ---- next-tile metadata + segment list ----
        const int tn = t + GRID;
        if (tid < TM && tn < NT) {
            const int ss = ssi[tn * TM + tid];
            ss2[par ^ 1][tid] = ss;
            gt2[par ^ 1][tid] = gates[ss];
            ex2[par ^ 1][tid] = sei[tn * TM + tid];
        }
        if (tid == 0) {
            int ns = 0, e = ex2[par][0];
            seg_e[ns++] = e;
            for (int i = 1; i < TM; ++i) {
                const int ei = ex2[par][i];
                if (ei != e) { e = ei; seg_e[ns++] = e; }
            }
            seg_n = ns;
        }
        __syncthreads();

        // ---- prefetch next tile's A into Araw ----
        if (tn < NT) {
            const uint32_t abase = smem_u32(Araw);
            #pragma unroll
            for (int it = 0; it < 8; ++it) {
                const int idx = tid + NTHR * it;
                const int m = idx >> 5, q = (idx & 31) * 4;
                cp16(abase + (uint32_t)(m * SAR + q) * 4,
                     inputs + (size_t)(ss2[par ^ 1][m] >> 1) * DIN + q);
            }
        }
        CP_COMMIT();

        // ---- expert segments ----
        const int nseg = seg_n;
        for (int s = 0; s < nseg; ++s) {
            const int e = seg_e[s];
            if (e != B_cur) {
                __syncthreads();   // all warps done reading old B_frag
                const int b = wid;
                const float* Wrow = weight + (size_t)e * DOUT * DIN + (b * 8 + gr) * DIN;
                uint2* dst2 = (uint2*)B_frag;   // 2 uint2 per uint4
                #pragma unroll
                for (int ks = 0; ks < 8; ++ks) {
                    const int k0 = ks * 16 + tc * 2;
                    const float2 w0 = *(const float2*)(Wrow + k0);
                    const float2 w1 = *(const float2*)(Wrow + k0 + 8);
                    uint2 f;
                    f.x = pack_h2(w0.x, w0.y);
                    f.y = pack_h2(w1.x, w1.y);
                    dst2[(((b >> 1) * 8 + ks) * 32 + lane) * 2 + (b & 1)] = f;
                }
                B_cur = e;
                __syncthreads();
            }

            // ---- MMA: warp tile 32(M) x 32(N), K=128, 8 ks slices ----
            float acc[2][4][4];
            #pragma unroll
            for (int mt = 0; mt < 2; ++mt)
                #pragma unroll
                for (int nt = 0; nt < 4; ++nt)
                    #pragma unroll
                    for (int j = 0; j < 4; ++j) acc[mt][nt][j] = 0.f;

            const int R0  = wm * 2;
            const int np0 = wn * 2;
            #pragma unroll
            for (int ks = 0; ks < 8; ++ks) {
                const uint4 A0 = As_frag[(R0 * 8 + ks) * 32 + lane];
                const uint4 A1 = As_frag[((R0 + 1) * 8 + ks) * 32 + lane];
                const uint4 B0 = B_frag[(np0 * 8 + ks) * 32 + lane];
                const uint4 B1 = B_frag[((np0 + 1) * 8 + ks) * 32 + lane];
                const uint32_t a0[4] = {A0.x, A0.y, A0.z, A0.w};
                const uint32_t a1[4] = {A1.x, A1.y, A1.z, A1.w};
                mma_f16(acc[0][0], a0, B0.x, B0.y);
                mma_f16(acc[0][1], a0, B0.z, B0.w);
                mma_f16(acc[0][2], a0, B1.x, B1.y);
                mma_f16(acc[0][3], a0, B1.z, B1.w);
                mma_f16(acc[1][0], a1, B0.x, B0.y);
                mma_f16(acc[1][1], a1, B0.z, B0.w);
                mma_f16(acc[1][2], a1, B1.x, B1.y);
                mma_f16(acc[1][3], a1, B1.z, B1.w);
            }

            // ---- epilogue: gate-scale + scatter rows (fp16 packed) ----
            #pragma unroll
            for (int mt = 0; mt < 2; ++mt) {
                #pragma unroll
                for (int half = 0; half < 2; ++half) {
                    const int m = wm * 32 + mt * 16 + gr + half * 8;
                    if (ex2[par][m] != e) continue;
                    const float g = gt2[par][m];
                    __half* dst = g_ybuf + (size_t)ss2[par][m] * DOUT + wn * 32 + 2 * tc;
                    #pragma unroll
                    for (int nt = 0; nt < 4; ++nt) {
                        const uint32_t h2 = pack_h2(acc[mt][nt][half * 2 + 0] * g,
                                                    acc[mt][nt][half * 2 + 1] * g);
                        *(uint32_t*)(dst + nt * 8) = h2;
                    }
                }
            }
        }

        par ^= 1;
        __syncthreads();   // epilogue done before buffers flip
    }

    // ================= grid barrier (sense-reversing, generation) ==========
    __threadfence();        // make this CTA's ybuf writes visible device-wide
    __syncthreads();
    if (tid == 0) {
        const unsigned my = g_gen;                 // read BEFORE arriving
        const unsigned a  = atomicAdd(&g_bar, 1u);
        if (a == GRID - 1) {
            g_bar = 0;                             // reset for next graph replay
            __threadfence();
            atomicAdd((unsigned*)&g_gen, 1u);      // release
        } else {
            while (g_gen == my) { }                // spin (volatile read)
        }
    }
    __syncthreads();
    __threadfence();        // acquire: see all CTAs' ybuf writes

    // ================= fused combine: out[t] = ybuf[2t] + ybuf[2t+1] =======
    {
        const int total = NTOK * 32;               // 16B output units
        for (int i = blockIdx.x * NTHR + tid; i < total; i += GRID * NTHR) {
            const int t = i >> 5;
            const int q = (i & 31) * 4;
            const __half2* a = (const __half2*)(g_ybuf + (size_t)(2 * t) * DOUT + q);
            const __half2* b = (const __half2*)(g_ybuf + (size_t)(2 * t + 1) * DOUT + q);
            const float2 a0 = __half22float2(a[0]);
            const float2 a1 = __half22float2(a[1]);
            const float2 b0 = __half22float2(b[0]);
            const float2 b1 = __half22float2(b[1]);
            float4 o;
            o.x = a0.x + b0.x; o.y = a0.y + b0.y;
            o.z = a1.x + b1.x; o.w = a1.y + b1.y;
            *(float4*)(out + (size_t)t * DOUT + q) = o;
        }
    }
}

// ---------------------------------------------------------------------------
extern "C" void kernel_launch(void* const* d_in, const int* in_sizes, int n_in,
                              void* d_out, int out_size)
{
    const float* inputs = (const float*)d_in[0];
    const float* weight = (const float*)d_in[1];
    const float* gates  = (const float*)d_in[2];

    int idxs[2] = {-1, -1};
    int found = 0;
    for (int i = 3; i < n_in && found < 2; ++i) {
        if (in_sizes[i] == 1) continue;   // scalar k
        idxs[found++] = i;
    }
    const int* sei = (const int*)d_in[idxs[0]];
    const int* ssi = (const int*)d_in[idxs[1]];
    float* out = (float*)d_out;
    (void)out_size;

    const int smem = 128 * SAR * 4 + 2 * 2048 * 16;   // 133120
    cudaFuncSetAttribute(k_moe, cudaFuncAttributeMaxDynamicSharedMemorySize, smem);

    k_moe<<<GRID, NTHR, smem>>>(inputs, weight, gates, sei, ssi, out);
}

// round 12
// speedup vs baseline: 1.3240x; 1.3240x over previous
#include <cuda_runtime.h>
#include <cuda_fp16.h>
#include <stdint.h>

#define NTOK   262144
#define NSLOT  524288
#define DIN    128
#define DOUT   128
#define NEXP   8
#define TM     64             // slot rows per tile
#define NT     (NSLOT / TM)   // 8192 tiles
#define GRID   296            // 2 CTAs per SM
#define NTHR   256
#define SAR    132            // Araw padded stride (floats)

typedef unsigned long long ull;

__device__ __half g_ybuf[(size_t)NSLOT * DOUT];   // gate-scaled per-slot outputs (fp16)

// ---------------------------------------------------------------------------
// helpers
// ---------------------------------------------------------------------------
__device__ __forceinline__ uint32_t smem_u32(const void* p) {
    uint32_t a;
    asm("{ .reg .u64 t; cvta.to.shared.u64 t, %1; cvt.u32.u64 %0, t; }" : "=r"(a) : "l"(p));
    return a;
}
// pack two fp32 -> fp16x2 (lo = x, hi = y)
__device__ __forceinline__ uint32_t pack_h2(float x, float y) {
    uint32_t u;
    asm("cvt.rn.f16x2.f32 %0, %1, %2;" : "=r"(u) : "f"(y), "f"(x));
    return u;
}
__device__ __forceinline__ void cp16(uint32_t dst, const void* src) {
    asm volatile("cp.async.ca.shared.global [%0], [%1], 16;" :: "r"(dst), "l"(src) : "memory");
}
#define CP_COMMIT() asm volatile("cp.async.commit_group;" ::: "memory")
#define CP_WAIT0()  asm volatile("cp.async.wait_group 0;" ::: "memory")

// m16n8k16 fp16 -> fp32 acc
__device__ __forceinline__ void mma_f16(float* d, const uint32_t* a, uint32_t b0, uint32_t b1) {
    asm volatile("mma.sync.aligned.m16n8k16.row.col.f32.f16.f16.f32 "
                 "{%0,%1,%2,%3}, {%4,%5,%6,%7}, {%8,%9}, {%0,%1,%2,%3};"
                 : "+f"(d[0]), "+f"(d[1]), "+f"(d[2]), "+f"(d[3])
                 : "r"(a[0]), "r"(a[1]), "r"(a[2]), "r"(a[3]), "r"(b0), "r"(b1));
}

// ---------------------------------------------------------------------------
// Persistent grouped-GEMM, 256 threads, 2 CTAs/SM (phase overlap across CTAs).
// Tile: M=64 slots x N=128 x K=128. Warp tile 16(M) x 64(N).
// smem: Araw f32[64][SAR] | As_frag uint4[4*8*32] | B_frag uint4[8*8*32]
//   As_frag[R(m16 blk 0..3)][ks][lane] = {a0,a1,a2,a3}
//   B_frag [np(n16 blk 0..7)][ks][lane] = {b of n8 blk 2np, b of 2np+1}
// ---------------------------------------------------------------------------
__global__ void __launch_bounds__(NTHR, 2)
k_moe(const float* __restrict__ inputs,
      const float* __restrict__ weight,   // [E][DOUT][DIN] == W[n][k] row-major
      const float* __restrict__ gates,    // flat [NSLOT]
      const int*   __restrict__ sei,
      const int*   __restrict__ ssi)
{
    extern __shared__ float smraw[];
    float* Araw    = smraw;                                  // 64*SAR f32
    uint4* As_frag = (uint4*)(smraw + TM * SAR);             // 1024 uint4
    uint4* B_frag  = As_frag + 4 * 8 * 32;                   // 2048 uint4

    __shared__ int   ss2[2][TM];
    __shared__ float gt2[2][TM];
    __shared__ int   ex2[2][TM];
    __shared__ int   seg_e[NEXP + 1];
    __shared__ int   seg_n;

    const int tid  = threadIdx.x;
    const int lane = tid & 31;
    const int wid  = tid >> 5;        // 0..7
    const int wm   = wid >> 1;        // 0..3 -> m16 block (rows wm*16)
    const int wn   = wid & 1;         // 0..1 -> cols wn*64
    const int gr   = lane >> 2;       // 0..7
    const int tc   = lane & 3;        // 0..3

    // ---- prologue: metadata + first A prefetch ----
    const int t0 = blockIdx.x;
    if (tid < TM) {
        const int ss = ssi[t0 * TM + tid];
        ss2[0][tid] = ss;
        gt2[0][tid] = gates[ss];
        ex2[0][tid] = sei[t0 * TM + tid];
    }
    __syncthreads();
    {
        const uint32_t abase = smem_u32(Araw);
        #pragma unroll
        for (int it = 0; it < 8; ++it) {
            const int idx = tid + NTHR * it;          // 2048 float4 units
            const int m = idx >> 5, q = (idx & 31) * 4;
            cp16(abase + (uint32_t)(m * SAR + q) * 4,
                 inputs + (size_t)(ss2[0][m] >> 1) * DIN + q);
        }
    }
    CP_COMMIT();

    int par = 0;
    int B_cur = -1;

    for (int t = t0; t < NT; t += GRID) {
        CP_WAIT0();
        __syncthreads();   // Araw ready; prior-tile MMA done with As_frag

        // ---- cvt Araw(fp32) -> As_frag(fp16 fragments) ----
        // warp w: R = w>>1 (0..3), ks in 4*(w&1) .. +3
        {
            const int R = wid >> 1;
            const int ks0 = (wid & 1) * 4;
            const int row = R * 16 + gr;
            #pragma unroll
            for (int i = 0; i < 4; ++i) {
                const int ks = ks0 + i;
                const int c0 = ks * 16 + tc * 2;
                const float2 v00 = *(const float2*)(Araw + row * SAR + c0);
                const float2 v10 = *(const float2*)(Araw + (row + 8) * SAR + c0);
                const float2 v01 = *(const float2*)(Araw + row * SAR + c0 + 8);
                const float2 v11 = *(const float2*)(Araw + (row + 8) * SAR + c0 + 8);
                uint4 f;
                f.x = pack_h2(v00.x, v00.y);
                f.y = pack_h2(v10.x, v10.y);
                f.z = pack_h2(v01.x, v01.y);
                f.w = pack_h2(v11.x, v11.y);
                As_frag[(R * 8 + ks) * 32 + lane] = f;
            }
        }
        __syncthreads();   // Araw free, As_frag ready

        // ---- next-tile metadata + segment list ----
        const int tn = t + GRID;
        if (tid < TM && tn < NT) {
            const int ss = ssi[tn * TM + tid];
            ss2[par ^ 1][tid] = ss;
            gt2[par ^ 1][tid] = gates[ss];
            ex2[par ^ 1][tid] = sei[tn * TM + tid];
        }
        if (tid == 0) {
            int ns = 0, e = ex2[par][0];
            seg_e[ns++] = e;
            for (int i = 1; i < TM; ++i) {
                const int ei = ex2[par][i];
                if (ei != e) { e = ei; seg_e[ns++] = e; }
            }
            seg_n = ns;
        }
        __syncthreads();

        // ---- prefetch next tile's A into Araw ----
        if (tn < NT) {
            const uint32_t abase = smem_u32(Araw);
            #pragma unroll
            for (int it = 0; it < 8; ++it) {
                const int idx = tid + NTHR * it;
                const int m = idx >> 5, q = (idx & 31) * 4;
                cp16(abase + (uint32_t)(m * SAR + q) * 4,
                     inputs + (size_t)(ss2[par ^ 1][m] >> 1) * DIN + q);
            }
        }
        CP_COMMIT();

        // ---- expert segments ----
        const int nseg = seg_n;
        for (int s = 0; s < nseg; ++s) {
            const int e = seg_e[s];
            if (e != B_cur) {
                __syncthreads();   // all warps done reading old B_frag
                // warp w converts n8 blocks {2w, 2w+1}
                uint2* dst2 = (uint2*)B_frag;   // 2 uint2 per uint4
                #pragma unroll
                for (int bb = 0; bb < 2; ++bb) {
                    const int b = wid * 2 + bb;
                    const float* Wrow = weight + (size_t)e * DOUT * DIN + (b * 8 + gr) * DIN;
                    #pragma unroll
                    for (int ks = 0; ks < 8; ++ks) {
                        const int k0 = ks * 16 + tc * 2;
                        const float2 w0 = *(const float2*)(Wrow + k0);
                        const float2 w1 = *(const float2*)(Wrow + k0 + 8);
                        uint2 f;
                        f.x = pack_h2(w0.x, w0.y);
                        f.y = pack_h2(w1.x, w1.y);
                        dst2[(((b >> 1) * 8 + ks) * 32 + lane) * 2 + (b & 1)] = f;
                    }
                }
                B_cur = e;
                __syncthreads();
            }

            // ---- MMA: warp tile 16(M) x 64(N), K=128, 8 ks slices ----
            float acc[8][4];
            #pragma unroll
            for (int nt = 0; nt < 8; ++nt)
                #pragma unroll
                for (int j = 0; j < 4; ++j) acc[nt][j] = 0.f;

            const int np0 = wn * 4;
            #pragma unroll
            for (int ks = 0; ks < 8; ++ks) {
                const uint4 A0 = As_frag[(wm * 8 + ks) * 32 + lane];
                const uint32_t a0[4] = {A0.x, A0.y, A0.z, A0.w};
                #pragma unroll
                for (int j = 0; j < 4; ++j) {
                    const uint4 B = B_frag[((np0 + j) * 8 + ks) * 32 + lane];
                    mma_f16(acc[j * 2 + 0], a0, B.x, B.y);
                    mma_f16(acc[j * 2 + 1], a0, B.z, B.w);
                }
            }

            // ---- epilogue: gate-scale + scatter rows (fp16 packed) ----
            #pragma unroll
            for (int half = 0; half < 2; ++half) {
                const int m = wm * 16 + gr + half * 8;
                if (ex2[par][m] != e) continue;
                const float g = gt2[par][m];
                __half* dst = g_ybuf + (size_t)ss2[par][m] * DOUT + wn * 64 + 2 * tc;
                #pragma unroll
                for (int nt = 0; nt < 8; ++nt) {
                    const uint32_t h2 = pack_h2(acc[nt][half * 2 + 0] * g,
                                                acc[nt][half * 2 + 1] * g);
                    *(uint32_t*)(dst + nt * 8) = h2;
                }
            }
        }

        par ^= 1;
        __syncthreads();   // epilogue done before buffers flip
    }
}

// ---------------------------------------------------------------------------
// Combine: out[t] = ybuf[2t] + ybuf[2t+1] (fp16 in, fp32 out; gates applied)
// ---------------------------------------------------------------------------
__global__ void k_combine(float* __restrict__ out) {
    const int i = blockIdx.x * 256 + threadIdx.x;   // 0 .. NTOK*32-1
    const int t = i >> 5;
    const int q = (i & 31) * 4;
    const __half2* a = (const __half2*)(g_ybuf + (size_t)(2 * t) * DOUT + q);
    const __half2* b = (const __half2*)(g_ybuf + (size_t)(2 * t + 1) * DOUT + q);
    const float2 a0 = __half22float2(a[0]);
    const float2 a1 = __half22float2(a[1]);
    const float2 b0 = __half22float2(b[0]);
    const float2 b1 = __half22float2(b[1]);
    float4 o;
    o.x = a0.x + b0.x; o.y = a0.y + b0.y;
    o.z = a1.x + b1.x; o.w = a1.y + b1.y;
    *(float4*)(out + (size_t)t * DOUT + q) = o;
}

// ---------------------------------------------------------------------------
extern "C" void kernel_launch(void* const* d_in, const int* in_sizes, int n_in,
                              void* d_out, int out_size)
{
    const float* inputs = (const float*)d_in[0];
    const float* weight = (const float*)d_in[1];
    const float* gates  = (const float*)d_in[2];

    int idxs[2] = {-1, -1};
    int found = 0;
    for (int i = 3; i < n_in && found < 2; ++i) {
        if (in_sizes[i] == 1) continue;   // scalar k
        idxs[found++] = i;
    }
    const int* sei = (const int*)d_in[idxs[0]];
    const int* ssi = (const int*)d_in[idxs[1]];
    float* out = (float*)d_out;
    (void)out_size;

    // Araw 64*132*4=33792 + As_frag 16384 + B_frag 32768 = 82944 per CTA
    const int smem = TM * SAR * 4 + 1024 * 16 + 2048 * 16;
    cudaFuncSetAttribute(k_moe, cudaFuncAttributeMaxDynamicSharedMemorySize, smem);

    k_moe<<<GRID, NTHR, smem>>>(inputs, weight, gates, sei, ssi);
    k_combine<<<(NTOK * 32) / 256, 256>>>(out);
}

// round 13
// speedup vs baseline: 1.3900x; 1.0498x over previous
#include <cuda_runtime.h>
#include <cuda_fp16.h>
#include <stdint.h>

#define NTOK   262144
#define NSLOT  524288
#define DIN    128
#define DOUT   128
#define NEXP   8
#define TM     64             // slot rows per tile
#define NT     (NSLOT / TM)   // 8192 tiles
#define GRID   444            // 3 CTAs per SM
#define NTHR   256

typedef unsigned long long ull;

__device__ __half g_ybuf[(size_t)NSLOT * DOUT];   // gate-scaled per-slot outputs (fp16)

// ---------------------------------------------------------------------------
// helpers
// ---------------------------------------------------------------------------
// pack two fp32 -> fp16x2 (lo = x, hi = y)
__device__ __forceinline__ uint32_t pack_h2(float x, float y) {
    uint32_t u;
    asm("cvt.rn.f16x2.f32 %0, %1, %2;" : "=r"(u) : "f"(y), "f"(x));
    return u;
}
// m16n8k16 fp16 -> fp32 acc
__device__ __forceinline__ void mma_f16(float* d, const uint32_t* a, uint32_t b0, uint32_t b1) {
    asm volatile("mma.sync.aligned.m16n8k16.row.col.f32.f16.f16.f32 "
                 "{%0,%1,%2,%3}, {%4,%5,%6,%7}, {%8,%9}, {%0,%1,%2,%3};"
                 : "+f"(d[0]), "+f"(d[1]), "+f"(d[2]), "+f"(d[3])
                 : "r"(a[0]), "r"(a[1]), "r"(a[2]), "r"(a[3]), "r"(b0), "r"(b1));
}

// ---------------------------------------------------------------------------
// Persistent grouped-GEMM, 256 threads, 3 CTAs/SM (cross-CTA phase overlap).
// Tile: M=64 slots x N=128 x K=128. Warp tile 16(M) x 64(N).
// A is gathered from gmem and converted to fp16 fragments in-flight (no fp32
// staging buffer) -> smem/CTA = 48 KB -> occupancy 3.
// smem: As_frag uint4[4*8*32] | B_frag uint4[8*8*32]
//   As_frag[R(m16 blk 0..3)][ks][lane] = {a0,a1,a2,a3}
//   B_frag [np(n16 blk 0..7)][ks][lane] = {b of n8 blk 2np, b of 2np+1}
// ---------------------------------------------------------------------------
__global__ void __launch_bounds__(NTHR, 3)
k_moe(const float* __restrict__ inputs,
      const float* __restrict__ weight,   // [E][DOUT][DIN] == W[n][k] row-major
      const float* __restrict__ gates,    // flat [NSLOT]
      const int*   __restrict__ sei,
      const int*   __restrict__ ssi)
{
    extern __shared__ uint4 smraw[];
    uint4* As_frag = smraw;                 // 1024 uint4 (16 KB)
    uint4* B_frag  = As_frag + 4 * 8 * 32;  // 2048 uint4 (32 KB)

    __shared__ int   ss2[2][TM];
    __shared__ float gt2[2][TM];
    __shared__ int   ex2[2][TM];
    __shared__ int   seg_e[NEXP + 1];
    __shared__ int   seg_n;

    const int tid  = threadIdx.x;
    const int lane = tid & 31;
    const int wid  = tid >> 5;        // 0..7
    const int wm   = wid >> 1;        // 0..3 -> m16 block (rows wm*16)
    const int wn   = wid & 1;         // 0..1 -> cols wn*64
    const int gr   = lane >> 2;       // 0..7
    const int tc   = lane & 3;        // 0..3

    // ---- prologue: metadata for first tile ----
    const int t0 = blockIdx.x;
    if (tid < TM) {
        const int ss = ssi[t0 * TM + tid];
        ss2[0][tid] = ss;
        gt2[0][tid] = gates[ss];
        ex2[0][tid] = sei[t0 * TM + tid];
    }
    __syncthreads();

    int par = 0;
    int B_cur = -1;

    for (int t = t0; t < NT; t += GRID) {
        // ---- gather A from gmem + cvt -> As_frag (fp16 fragments) ----
        // warp w: R = w>>1 (0..3), ks in 4*(w&1)..+3; rows {R*16+gr, +8}
        {
            const int R   = wid >> 1;
            const int ks0 = (wid & 1) * 4;
            const int r0  = R * 16 + gr;
            const float* __restrict__ row0 = inputs + (size_t)(ss2[par][r0]     >> 1) * DIN;
            const float* __restrict__ row1 = inputs + (size_t)(ss2[par][r0 + 8] >> 1) * DIN;
            #pragma unroll
            for (int i = 0; i < 4; ++i) {
                const int ks = ks0 + i;
                const int c0 = ks * 16 + tc * 2;
                const float2 v00 = *(const float2*)(row0 + c0);
                const float2 v10 = *(const float2*)(row1 + c0);
                const float2 v01 = *(const float2*)(row0 + c0 + 8);
                const float2 v11 = *(const float2*)(row1 + c0 + 8);
                uint4 f;
                f.x = pack_h2(v00.x, v00.y);
                f.y = pack_h2(v10.x, v10.y);
                f.z = pack_h2(v01.x, v01.y);
                f.w = pack_h2(v11.x, v11.y);
                As_frag[(R * 8 + ks) * 32 + lane] = f;
            }
        }

        // ---- next-tile metadata + segment list (concurrent with gather) ----
        const int tn = t + GRID;
        if (tid < TM && tn < NT) {
            const int ss = ssi[tn * TM + tid];
            ss2[par ^ 1][tid] = ss;
            gt2[par ^ 1][tid] = gates[ss];
            ex2[par ^ 1][tid] = sei[tn * TM + tid];
        }
        if (tid == 0) {
            int ns = 0, e = ex2[par][0];
            seg_e[ns++] = e;
            for (int i = 1; i < TM; ++i) {
                const int ei = ex2[par][i];
                if (ei != e) { e = ei; seg_e[ns++] = e; }
            }
            seg_n = ns;
        }
        __syncthreads();   // As_frag ready, seg list ready

        // ---- expert segments ----
        const int nseg = seg_n;
        for (int s = 0; s < nseg; ++s) {
            const int e = seg_e[s];
            if (e != B_cur) {
                __syncthreads();   // all warps done reading old B_frag
                // warp w converts n8 blocks {2w, 2w+1}
                uint2* dst2 = (uint2*)B_frag;   // 2 uint2 per uint4
                #pragma unroll
                for (int bb = 0; bb < 2; ++bb) {
                    const int b = wid * 2 + bb;
                    const float* Wrow = weight + (size_t)e * DOUT * DIN + (b * 8 + gr) * DIN;
                    #pragma unroll
                    for (int ks = 0; ks < 8; ++ks) {
                        const int k0 = ks * 16 + tc * 2;
                        const float2 w0 = *(const float2*)(Wrow + k0);
                        const float2 w1 = *(const float2*)(Wrow + k0 + 8);
                        uint2 f;
                        f.x = pack_h2(w0.x, w0.y);
                        f.y = pack_h2(w1.x, w1.y);
                        dst2[(((b >> 1) * 8 + ks) * 32 + lane) * 2 + (b & 1)] = f;
                    }
                }
                B_cur = e;
                __syncthreads();
            }

            // ---- MMA: warp tile 16(M) x 64(N), K=128, 8 ks slices ----
            float acc[8][4];
            #pragma unroll
            for (int nt = 0; nt < 8; ++nt)
                #pragma unroll
                for (int j = 0; j < 4; ++j) acc[nt][j] = 0.f;

            const int np0 = wn * 4;
            #pragma unroll
            for (int ks = 0; ks < 8; ++ks) {
                const uint4 A0 = As_frag[(wm * 8 + ks) * 32 + lane];
                const uint32_t a0[4] = {A0.x, A0.y, A0.z, A0.w};
                #pragma unroll
                for (int j = 0; j < 4; ++j) {
                    const uint4 B = B_frag[((np0 + j) * 8 + ks) * 32 + lane];
                    mma_f16(acc[j * 2 + 0], a0, B.x, B.y);
                    mma_f16(acc[j * 2 + 1], a0, B.z, B.w);
                }
            }

            // ---- epilogue: gate-scale + scatter rows (fp16 packed) ----
            #pragma unroll
            for (int half = 0; half < 2; ++half) {
                const int m = wm * 16 + gr + half * 8;
                if (ex2[par][m] != e) continue;
                const float g = gt2[par][m];
                __half* dst = g_ybuf + (size_t)ss2[par][m] * DOUT + wn * 64 + 2 * tc;
                #pragma unroll
                for (int nt = 0; nt < 8; ++nt) {
                    const uint32_t h2 = pack_h2(acc[nt][half * 2 + 0] * g,
                                                acc[nt][half * 2 + 1] * g);
                    *(uint32_t*)(dst + nt * 8) = h2;
                }
            }
        }

        par ^= 1;
        __syncthreads();   // all reads of As_frag/metadata done before next iter
    }
}

// ---------------------------------------------------------------------------
// Combine: out[t] = ybuf[2t] + ybuf[2t+1] (fp16 in, fp32 out; gates applied)
// ---------------------------------------------------------------------------
__global__ void k_combine(float* __restrict__ out) {
    const int i = blockIdx.x * 256 + threadIdx.x;   // 0 .. NTOK*32-1
    const int t = i >> 5;
    const int q = (i & 31) * 4;
    const __half2* a = (const __half2*)(g_ybuf + (size_t)(2 * t) * DOUT + q);
    const __half2* b = (const __half2*)(g_ybuf + (size_t)(2 * t + 1) * DOUT + q);
    const float2 a0 = __half22float2(a[0]);
    const float2 a1 = __half22float2(a[1]);
    const float2 b0 = __half22float2(b[0]);
    const float2 b1 = __half22float2(b[1]);
    float4 o;
    o.x = a0.x + b0.x; o.y = a0.y + b0.y;
    o.z = a1.x + b1.x; o.w = a1.y + b1.y;
    *(float4*)(out + (size_t)t * DOUT + q) = o;
}

// ---------------------------------------------------------------------------
extern "C" void kernel_launch(void* const* d_in, const int* in_sizes, int n_in,
                              void* d_out, int out_size)
{
    const float* inputs = (const float*)d_in[0];
    const float* weight = (const float*)d_in[1];
    const float* gates  = (const float*)d_in[2];

    int idxs[2] = {-1, -1};
    int found = 0;
    for (int i = 3; i < n_in && found < 2; ++i) {
        if (in_sizes[i] == 1) continue;   // scalar k
        idxs[found++] = i;
    }
    const int* sei = (const int*)d_in[idxs[0]];
    const int* ssi = (const int*)d_in[idxs[1]];
    float* out = (float*)d_out;
    (void)out_size;

    // As_frag 16384 + B_frag 32768 = 49152 per CTA (3 CTAs/SM)
    const int smem = 1024 * 16 + 2048 * 16;
    cudaFuncSetAttribute(k_moe, cudaFuncAttributeMaxDynamicSharedMemorySize, smem);

    k_moe<<<GRID, NTHR, smem>>>(inputs, weight, gates, sei, ssi);
    k_combine<<<(NTOK * 32) / 256, 256>>>(out);
}